// round 6
// baseline (speedup 1.0000x reference)
#include <cuda_runtime.h>
#include <cuda_fp16.h>
#include <math.h>
#include <stdint.h>

#define B_TOK 65536
#define D_DIM 4096
#define E_EXP 64
#define K_TOP 8

#define TM   128
#define NBLK (B_TOK / TM)        // 512 CTAs
#define KC   32                  // K per chunk (64B rows, SW64)
#define NCH  (D_DIM / KC)        // 128 chunks
#define NCOL 128

// w pre-split (x64 scale keeps lo parts normal-range), [n][k] K-major
__device__ __half g_wh[NCOL * D_DIM];
__device__ __half g_wl[NCOL * D_DIM];
__device__ double g_ps[NBLK];
__device__ double g_sq[NBLK];

// ---- smem layout ----
// X buf b (b=0,1): hi at b*16384, lo at b*16384+8192        (32KB)
// W buf w (w=0,1,2): hi at 32768+w*16384, lo +8192          (48KB)
// epilogue overlay: LG 0 float[128][129] | NSRS 66048 float[128][65]
#define XB_OFF(b) ((b) * 16384)
#define WB_OFF(w) (32768 + (w) * 16384)
#define LG_OFF 0
#define NS_OFF 66048
#define SMEM_BYTES (66048 + 33280)   // 99328; occ 2 -> 194KB < 228KB

static __device__ __forceinline__ uint32_t smem_u32(const void* p) {
    uint32_t a;
    asm("{ .reg .u64 t; cvta.to.shared.u64 t, %1; cvt.u32.u64 %0, t; }" : "=r"(a) : "l"(p));
    return a;
}
static __device__ __forceinline__ uint32_t sw64(uint32_t off) { return off ^ ((off >> 3) & 0x30); }
static __device__ __forceinline__ uint32_t pkh(__half a, __half b) {
    return (uint32_t)__half_as_ushort(a) | ((uint32_t)__half_as_ushort(b) << 16);
}

#define LDSM4(r, a) \
    asm volatile("ldmatrix.sync.aligned.m8n8.x4.shared.b16 {%0,%1,%2,%3}, [%4];" \
        : "=r"((r)[0]), "=r"((r)[1]), "=r"((r)[2]), "=r"((r)[3]) : "r"(a))

static __device__ __forceinline__ void mma16816(float* d, const uint32_t* a, uint32_t b0, uint32_t b1) {
    asm volatile("mma.sync.aligned.m16n8k16.row.col.f32.f16.f16.f32 "
        "{%0,%1,%2,%3}, {%4,%5,%6,%7}, {%8,%9}, {%0,%1,%2,%3};"
        : "+f"(d[0]), "+f"(d[1]), "+f"(d[2]), "+f"(d[3])
        : "r"(a[0]), "r"(a[1]), "r"(a[2]), "r"(a[3]), "r"(b0), "r"(b1));
}

#define CP_ASYNC16(dst, src) asm volatile("cp.async.cg.shared.global [%0], [%1], 16;" :: "r"(dst), "l"(src) : "memory")
#define CP_COMMIT()          asm volatile("cp.async.commit_group;" ::: "memory")
#define CP_WAIT1()           asm volatile("cp.async.wait_group 1;" ::: "memory")
#define CP_WAIT0()           asm volatile("cp.async.wait_group 0;" ::: "memory")

// ---- split w_gate|w_noise (x64) -> fp16 hi/lo, [n][k] ----
__global__ void wconv_kernel(const float* __restrict__ wg, const float* __restrict__ wn)
{
    int idx = blockIdx.x * 256 + threadIdx.x;
    if (idx >= D_DIM * E_EXP) return;
    int k = idx >> 6, n = idx & 63;
    float f = wg[idx] * 64.f;
    __half h = __float2half(f);
    g_wh[(size_t)n * D_DIM + k] = h;
    g_wl[(size_t)n * D_DIM + k] = __float2half(f - __half2float(h));
    f = wn[idx] * 64.f;
    h = __float2half(f);
    g_wh[(size_t)(64 + n) * D_DIM + k] = h;
    g_wl[(size_t)(64 + n) * D_DIM + k] = __float2half(f - __half2float(h));
}

// 1024 x 16B per chunk (512 hi + 512 lo), 4 per thread
static __device__ __forceinline__ void issue_w(uint32_t sb, int t, int k0, int wb) {
    uint32_t base = sb + WB_OFF(wb);
#pragma unroll
    for (int i = 0; i < 4; i++) {
        int idx = t + (i << 8);                  // 0..1023
        int v   = idx >> 9;                      // 0 hi, 1 lo
        int rem = idx & 511;
        int n = rem >> 2, q = rem & 3;
        const __half* src = (v ? g_wl : g_wh) + (size_t)n * D_DIM + k0 + (q << 3);
        uint32_t dst = base + (v << 13) + sw64((n << 6) + (q << 4));
        CP_ASYNC16(dst, src);
    }
}

__global__ __launch_bounds__(256, 2)
void gate_mma_kernel(const float* __restrict__ x,
                     const float* __restrict__ noise,
                     float* __restrict__ out, int out_elems)
{
    extern __shared__ char smem[];
    const uint32_t sb = smem_u32(smem);
    const int t   = threadIdx.x;
    const int wid = t >> 5;
    const int lid = t & 31;
    const int wm  = wid & 1;
    const int wn  = wid >> 1;
    const int row0 = blockIdx.x * TM;
    const float* xp = x + (size_t)row0 * D_DIM;

    float acc[4][4][4];
#pragma unroll
    for (int a = 0; a < 4; a++)
#pragma unroll
        for (int b = 0; b < 4; b++)
#pragma unroll
            for (int c = 0; c < 4; c++) acc[a][b][c] = 0.f;

    // ldmatrix addressing (64B rows): xor mask = (r&6)<<3, r low bits = lid low bits
    const uint32_t xmask     = (uint32_t)(lid & 6) << 3;
    const uint32_t a_rowbase = (uint32_t)(wm * 64 + ((lid >> 3) & 1) * 8 + (lid & 7)) * 64;
    const uint32_t a_kincr   = (uint32_t)(lid >> 4) * 16;
    const uint32_t b_rowbase = (uint32_t)(wn * 32 + ((lid >> 4) << 3) + (lid & 7)) * 64;
    const uint32_t b_kincr   = (uint32_t)((lid >> 3) & 1) * 16;

    // x tile: 1024 float4 per chunk, 4 per thread: row = idx>>3, col4 = idx&7
    const int xr_ = t >> 3;                // rows xr_, xr_+32, +64, +96
    const int xj_ = t & 7;

    // x store helper data
    auto store_x = [&](const float4* v, int xb) {
#pragma unroll
        for (int i = 0; i < 4; i++) {
            int r = xr_ + (i << 5);
            __half h0 = __float2half(v[i].x), h1 = __float2half(v[i].y);
            __half h2 = __float2half(v[i].z), h3 = __float2half(v[i].w);
            __half l0 = __float2half(v[i].x - __half2float(h0)), l1 = __float2half(v[i].y - __half2float(h1));
            __half l2 = __float2half(v[i].z - __half2float(h2)), l3 = __float2half(v[i].w - __half2float(h3));
            uint32_t sw = sw64((r << 6) + (xj_ << 3));
            *(uint2*)(smem + XB_OFF(xb) + sw)        = make_uint2(pkh(h0, h1), pkh(h2, h3));
            *(uint2*)(smem + XB_OFF(xb) + 8192 + sw) = make_uint2(pkh(l0, l1), pkh(l2, l3));
        }
    };

    // ---- prologue: w(0)->W0, w(1)->W1 in flight; x(0)->X0 stored ----
    issue_w(sb, t, 0, 0); CP_COMMIT();
    issue_w(sb, t, KC, 1); CP_COMMIT();
    {
        float4 v[4];
#pragma unroll
        for (int i = 0; i < 4; i++)
            v[i] = *(const float4*)(xp + (size_t)(xr_ + (i << 5)) * D_DIM + (xj_ << 2));
        store_x(v, 0);
    }
    CP_WAIT1();                 // w(0) arrived
    __syncthreads();

    for (int c = 0; c < NCH; ++c) {
        const int xb = c & 1;
        const uint32_t wb = sb + WB_OFF(c % 3);

        if (c + 2 < NCH) { issue_w(sb, t, (c + 2) * KC, (c + 2) % 3); CP_COMMIT(); }

        // prefetch next x into regs (latency hides under MMA)
        float4 v[4];
        if (c + 1 < NCH) {
            const int k0n = (c + 1) * KC;
#pragma unroll
            for (int i = 0; i < 4; i++)
                v[i] = *(const float4*)(xp + (size_t)(xr_ + (i << 5)) * D_DIM + k0n + (xj_ << 2));
        }

        // ---- MMA on buffer c ----
#pragma unroll
        for (int ks = 0; ks < 2; ++ks) {
            const uint32_t boff = (uint32_t)(ks * 32 + b_kincr) ^ xmask;
            uint32_t bH[8], bL[8];
            LDSM4(&bH[0], wb + b_rowbase + boff);
            LDSM4(&bH[4], wb + b_rowbase + 1024 + boff);
            LDSM4(&bL[0], wb + 8192 + b_rowbase + boff);
            LDSM4(&bL[4], wb + 8192 + b_rowbase + 1024 + boff);
            const uint32_t aoff = (uint32_t)(ks * 32 + a_kincr) ^ xmask;
#pragma unroll
            for (int mt = 0; mt < 4; ++mt) {
                uint32_t aH[4], aL[4];
                LDSM4(aH, sb + XB_OFF(xb) + a_rowbase + mt * 1024 + aoff);
                LDSM4(aL, sb + XB_OFF(xb) + 8192 + a_rowbase + mt * 1024 + aoff);
#pragma unroll
                for (int nt = 0; nt < 4; ++nt) {
                    int bi = (nt >> 1) * 4 + (nt & 1) * 2;
                    mma16816(acc[mt][nt], aH, bH[bi], bH[bi + 1]);
                    mma16816(acc[mt][nt], aH, bL[bi], bL[bi + 1]);
                    mma16816(acc[mt][nt], aL, bH[bi], bH[bi + 1]);
                }
            }
        }

        if (c + 1 < NCH) store_x(v, xb ^ 1);
        if (c + 2 < NCH) CP_WAIT1(); else CP_WAIT0();
        __syncthreads();
    }

    // ================= epilogue =================
    float* lg   = (float*)(smem + LG_OFF);
    float* nsrs = (float*)(smem + NS_OFF);

#pragma unroll
    for (int i = 0; i < 32; i++) {
        int idx = t + (i << 8);
        nsrs[(idx >> 6) * 65 + (idx & 63)] = noise[(size_t)row0 * E_EXP + idx];
    }
#pragma unroll
    for (int mt = 0; mt < 4; ++mt) {
        int r = wm * 64 + mt * 16 + (lid >> 2);
#pragma unroll
        for (int nt = 0; nt < 4; ++nt) {
            int c0 = wn * 32 + nt * 8 + (lid & 3) * 2;
            lg[r * 129 + c0]           = acc[mt][nt][0];
            lg[r * 129 + c0 + 1]       = acc[mt][nt][1];
            lg[(r + 8) * 129 + c0]     = acc[mt][nt][2];
            lg[(r + 8) * 129 + c0 + 1] = acc[mt][nt][3];
        }
    }
    __syncthreads();

    double ps_d = 0.0, sq_d = 0.0;
    if (t < TM) {
        const int r = t;
        float m = -INFINITY;
        for (int e = 0; e < E_EXP; ++e) {
            float cl = lg[r * 129 + e]      * 0.015625f;
            float nr = lg[r * 129 + 64 + e] * 0.015625f;
            float sd = (nr > 20.f) ? nr : log1pf(__expf(nr));
            float v  = cl + nsrs[r * 65 + e] * sd;
            lg[r * 129 + e] = v;
            m = fmaxf(m, v);
        }
        float s = 0.f;
        for (int e = 0; e < E_EXP; ++e) s += __expf(lg[r * 129 + e] - m);
        float inv = 1.f / s;
        float ps = 0.f, sq = 0.f;
        for (int e = 0; e < E_EXP; ++e) {
            float p = __expf(lg[r * 129 + e] - m) * inv;
            ps += p; sq += p * p;
        }
        ps_d = ps; sq_d = sq;

        unsigned long long sel = 0ULL;
        float m8 = 0.f;
        for (int kk = 0; kk < K_TOP; ++kk) {
            float best = -INFINITY; int bi = 0;
            for (int e = 0; e < E_EXP; ++e) {
                if (!((sel >> e) & 1ULL)) {
                    float v = lg[r * 129 + e];
                    if (v > best) { best = v; bi = e; }
                }
            }
            sel |= 1ULL << bi;
            if (kk == 0) m8 = best;
        }
        float s8 = 0.f;
        for (int e = 0; e < E_EXP; ++e)
            if ((sel >> e) & 1ULL) s8 += __expf(lg[r * 129 + e] - m8);
        float inv8 = 1.f / s8;
        for (int e = 0; e < E_EXP; ++e)
            nsrs[r * 65 + e] = ((sel >> e) & 1ULL) ? __expf(lg[r * 129 + e] - m8) * inv8 : 0.f;
    }

    __shared__ double wps[4], wsq[4];
#pragma unroll
    for (int o = 16; o > 0; o >>= 1) {
        ps_d += __shfl_down_sync(0xffffffffu, ps_d, o);
        sq_d += __shfl_down_sync(0xffffffffu, sq_d, o);
    }
    if (wid < 4 && lid == 0) { wps[wid] = ps_d; wsq[wid] = sq_d; }
    __syncthreads();
    if (t == 0) {
        g_ps[blockIdx.x] = wps[0] + wps[1] + wps[2] + wps[3];
        g_sq[blockIdx.x] = wsq[0] + wsq[1] + wsq[2] + wsq[3];
    }
#pragma unroll
    for (int i = 0; i < 32; i++) {
        int idx = t + (i << 8);
        size_t o = (size_t)row0 * E_EXP + idx;
        if (o < (size_t)out_elems) out[o] = nsrs[(idx >> 6) * 65 + (idx & 63)];
    }
}

__global__ void finalize_kernel(float* __restrict__ out, int out_elems)
{
    __shared__ double ssum[256], ssq[256];
    double a = 0.0, b = 0.0;
    for (int i = threadIdx.x; i < NBLK; i += 256) { a += g_ps[i]; b += g_sq[i]; }
    ssum[threadIdx.x] = a; ssq[threadIdx.x] = b;
    __syncthreads();
    for (int s = 128; s > 0; s >>= 1) {
        if (threadIdx.x < s) {
            ssum[threadIdx.x] += ssum[threadIdx.x + s];
            ssq[threadIdx.x]  += ssq[threadIdx.x + s];
        }
        __syncthreads();
    }
    if (threadIdx.x == 0) {
        double n    = (double)B_TOK * (double)E_EXP;
        double mean = ssum[0] / n;
        double var  = (ssq[0] - n * mean * mean) / (n - 1.0);
        float loss  = (float)(var / (mean * mean + 1e-10));
        long long base = (long long)B_TOK * E_EXP;
        if (out_elems == 1) out[0] = loss;
        else for (long long i = base; i < (long long)out_elems; i++) out[i] = loss;
    }
}

extern "C" void kernel_launch(void* const* d_in, const int* in_sizes, int n_in,
                              void* d_out, int out_size)
{
    const float* x  = (const float*)d_in[0];
    const float* wg = (const float*)d_in[1];
    const float* wn = (const float*)d_in[2];
    const float* nz = (const float*)d_in[3];
    float* out = (float*)d_out;

    cudaFuncSetAttribute(gate_mma_kernel, cudaFuncAttributeMaxDynamicSharedMemorySize, SMEM_BYTES);

    wconv_kernel<<<(D_DIM * E_EXP + 255) / 256, 256>>>(wg, wn);
    gate_mma_kernel<<<NBLK, 256, SMEM_BYTES>>>(x, nz, out, out_size);
    finalize_kernel<<<1, 256>>>(out, out_size);
}

// round 8
// speedup vs baseline: 1.1917x; 1.1917x over previous
#include <cuda_runtime.h>
#include <cuda_fp16.h>
#include <math.h>
#include <stdint.h>

#define B_TOK 65536
#define D_DIM 4096
#define E_EXP 64
#define K_TOP 8

#define TM   128
#define NBLK (B_TOK / TM)        // 512 CTAs
#define KC   64                  // K per chunk (128B rows, SW128)
#define NCH  (D_DIM / KC)        // 64 chunks
#define NCOL 128

// w pre-split (x64 scale keeps lo parts fp16-normal), [n][k] K-major
__device__ __half g_wh[NCOL * D_DIM];
__device__ __half g_wl[NCOL * D_DIM];
__device__ double g_ps[NBLK];
__device__ double g_sq[NBLK];

// ---- smem layout (occ1) ----
// X buf b (0,1): hi at b*32768, lo at +16384                 (64KB)
// W buf w (0,1,2): hi at 65536 + w*32768, lo at +16384       (96KB)
// epilogue overlay: LG 0 float[128][129] | NSRS 66048 float[128][65]
#define XB_OFF(b) ((b) * 32768)
#define WB_OFF(w) (65536 + (w) * 32768)
#define LG_OFF 0
#define NS_OFF 66048
#define SMEM_BYTES 163840

static __device__ __forceinline__ uint32_t smem_u32(const void* p) {
    uint32_t a;
    asm("{ .reg .u64 t; cvta.to.shared.u64 t, %1; cvt.u32.u64 %0, t; }" : "=r"(a) : "l"(p));
    return a;
}
static __device__ __forceinline__ uint32_t sw128(uint32_t off) { return off ^ ((off >> 3) & 0x70); }
static __device__ __forceinline__ uint32_t pkh(__half a, __half b) {
    return (uint32_t)__half_as_ushort(a) | ((uint32_t)__half_as_ushort(b) << 16);
}

#define LDSM4(r, a) \
    asm volatile("ldmatrix.sync.aligned.m8n8.x4.shared.b16 {%0,%1,%2,%3}, [%4];" \
        : "=r"((r)[0]), "=r"((r)[1]), "=r"((r)[2]), "=r"((r)[3]) : "r"(a))

static __device__ __forceinline__ void mma16816(float* d, const uint32_t* a, uint32_t b0, uint32_t b1) {
    asm volatile("mma.sync.aligned.m16n8k16.row.col.f32.f16.f16.f32 "
        "{%0,%1,%2,%3}, {%4,%5,%6,%7}, {%8,%9}, {%0,%1,%2,%3};"
        : "+f"(d[0]), "+f"(d[1]), "+f"(d[2]), "+f"(d[3])
        : "r"(a[0]), "r"(a[1]), "r"(a[2]), "r"(a[3]), "r"(b0), "r"(b1));
}

#define CP_ASYNC16(dst, src) asm volatile("cp.async.cg.shared.global [%0], [%1], 16;" :: "r"(dst), "l"(src) : "memory")
#define CP_COMMIT()          asm volatile("cp.async.commit_group;" ::: "memory")
#define CP_WAIT1()           asm volatile("cp.async.wait_group 1;" ::: "memory")
#define CP_WAIT0()           asm volatile("cp.async.wait_group 0;" ::: "memory")

// ---- split w_gate|w_noise (x64) -> fp16 hi/lo, [n][k] ----
__global__ void wconv_kernel(const float* __restrict__ wg, const float* __restrict__ wn)
{
    int idx = blockIdx.x * 256 + threadIdx.x;
    if (idx >= D_DIM * E_EXP) return;
    int k = idx >> 6, n = idx & 63;
    float f = wg[idx] * 64.f;
    __half h = __float2half(f);
    g_wh[(size_t)n * D_DIM + k] = h;
    g_wl[(size_t)n * D_DIM + k] = __float2half(f - __half2float(h));
    f = wn[idx] * 64.f;
    h = __float2half(f);
    g_wh[(size_t)(64 + n) * D_DIM + k] = h;
    g_wl[(size_t)(64 + n) * D_DIM + k] = __float2half(f - __half2float(h));
}

// w chunk: 2048 x 16B (1024 hi + 1024 lo); 512 threads -> 4 each
static __device__ __forceinline__ void issue_w(uint32_t sb, int t, int k0, int wb) {
    uint32_t base = sb + WB_OFF(wb);
#pragma unroll
    for (int i = 0; i < 4; i++) {
        int idx = t + (i << 9);                  // 0..2047
        int v   = idx >> 10;                     // 0 hi, 1 lo
        int rem = idx & 1023;
        int n = rem >> 3, q = rem & 7;
        const __half* src = (v ? g_wl : g_wh) + (size_t)n * D_DIM + k0 + (q << 3);
        uint32_t dst = base + (v << 14) + sw128((n << 7) + (q << 4));
        CP_ASYNC16(dst, src);
    }
}

__global__ __launch_bounds__(512, 1)
void gate_mma_kernel(const float* __restrict__ x,
                     const float* __restrict__ noise,
                     float* __restrict__ out, int out_elems)
{
    extern __shared__ char smem[];
    const uint32_t sb = smem_u32(smem);
    const int t   = threadIdx.x;
    const int wid = t >> 5;
    const int lid = t & 31;
    const int wm  = wid & 3;          // 32-row group
    const int wn  = wid >> 2;         // 32-col group
    const int row0 = blockIdx.x * TM;
    const float* xp = x + (size_t)row0 * D_DIM;

    float acc[2][4][4];
#pragma unroll
    for (int a = 0; a < 2; a++)
#pragma unroll
        for (int b = 0; b < 4; b++)
#pragma unroll
            for (int c = 0; c < 4; c++) acc[a][b][c] = 0.f;

    // ldmatrix addressing (128B rows)
    const uint32_t xmask     = (uint32_t)(lid & 7) << 4;
    const uint32_t a_rowbase = (uint32_t)(wm * 32 + ((lid >> 3) & 1) * 8 + (lid & 7)) * 128;
    const uint32_t a_kincr   = (uint32_t)(lid >> 4) * 16;
    const uint32_t b_rowbase = (uint32_t)(wn * 32 + ((lid >> 4) << 3) + (lid & 7)) * 128;
    const uint32_t b_kincr   = (uint32_t)((lid >> 3) & 1) * 16;

    // x tile: 2048 float4/chunk; 512 threads -> 4 each
    const int xr_ = t >> 4;
    const int xj_ = t & 15;

    auto store_x = [&](const float4* v, int xb) {
#pragma unroll
        for (int i = 0; i < 4; i++) {
            int r = xr_ + (i << 5);
            __half h0 = __float2half(v[i].x), h1 = __float2half(v[i].y);
            __half h2 = __float2half(v[i].z), h3 = __float2half(v[i].w);
            __half l0 = __float2half(v[i].x - __half2float(h0)), l1 = __float2half(v[i].y - __half2float(h1));
            __half l2 = __float2half(v[i].z - __half2float(h2)), l3 = __float2half(v[i].w - __half2float(h3));
            uint32_t sw = sw128((r << 7) + (xj_ << 3));
            *(uint2*)(smem + XB_OFF(xb) + sw)         = make_uint2(pkh(h0, h1), pkh(h2, h3));
            *(uint2*)(smem + XB_OFF(xb) + 16384 + sw) = make_uint2(pkh(l0, l1), pkh(l2, l3));
        }
    };

    // ---- prologue: w(0), w(1) in flight; x(0) -> X0 ----
    issue_w(sb, t, 0,  0); CP_COMMIT();
    issue_w(sb, t, KC, 1); CP_COMMIT();
    {
        float4 v[4];
#pragma unroll
        for (int i = 0; i < 4; i++)
            v[i] = *(const float4*)(xp + (size_t)(xr_ + (i << 5)) * D_DIM + (xj_ << 2));
        store_x(v, 0);
    }
    CP_WAIT1();                       // w(0) arrived
    __syncthreads();

    for (int c = 0; c < NCH; ++c) {
        const int xb = c & 1;
        const uint32_t wb = sb + WB_OFF(c % 3);

        // prefetch distance 2: WB((c+2)%3) was read by MMA(c-1), drained by last sync
        if (c + 2 < NCH) { issue_w(sb, t, (c + 2) * KC, (c + 2) % 3); CP_COMMIT(); }

        // prefetch next x into regs (hides under MMA below)
        float4 v[4];
        if (c + 1 < NCH) {
            const int k0n = (c + 1) * KC;
#pragma unroll
            for (int i = 0; i < 4; i++)
                v[i] = *(const float4*)(xp + (size_t)(xr_ + (i << 5)) * D_DIM + k0n + (xj_ << 2));
        }

        // ---- MMA on x buffer xb, w buffer c%3 ----
#pragma unroll
        for (int ks = 0; ks < 4; ++ks) {
            const uint32_t boff = (uint32_t)(ks * 32 + b_kincr) ^ xmask;
            uint32_t bH[8], bL[8];
            LDSM4(&bH[0], wb + b_rowbase + boff);
            LDSM4(&bH[4], wb + b_rowbase + 2048 + boff);
            LDSM4(&bL[0], wb + 16384 + b_rowbase + boff);
            LDSM4(&bL[4], wb + 16384 + b_rowbase + 2048 + boff);
            const uint32_t aoff = (uint32_t)(ks * 32 + a_kincr) ^ xmask;
#pragma unroll
            for (int mt = 0; mt < 2; ++mt) {
                uint32_t aH[4], aL[4];
                LDSM4(aH, sb + XB_OFF(xb) + a_rowbase + mt * 2048 + aoff);
                LDSM4(aL, sb + XB_OFF(xb) + 16384 + a_rowbase + mt * 2048 + aoff);
#pragma unroll
                for (int nt = 0; nt < 4; ++nt) {
                    int bi = (nt >> 1) * 4 + (nt & 1) * 2;
                    mma16816(acc[mt][nt], aH, bH[bi], bH[bi + 1]);
                    mma16816(acc[mt][nt], aH, bL[bi], bL[bi + 1]);
                    mma16816(acc[mt][nt], aL, bH[bi], bH[bi + 1]);
                }
            }
        }

        // store next x into the other buffer (its readers drained by last sync)
        if (c + 1 < NCH) store_x(v, xb ^ 1);
        if      (c + 2 < NCH) CP_WAIT1();    // w(c+1) arrived; w(c+2) may fly
        else if (c + 1 < NCH) CP_WAIT0();
        __syncthreads();
    }

    // ================= epilogue =================
    float* lg   = (float*)(smem + LG_OFF);        // [128][129]
    float* nsrs = (float*)(smem + NS_OFF);        // [128][65]

#pragma unroll
    for (int i = 0; i < 16; i++) {
        int idx = t + (i << 9);
        nsrs[(idx >> 6) * 65 + (idx & 63)] = noise[(size_t)row0 * E_EXP + idx];
    }
#pragma unroll
    for (int mt = 0; mt < 2; ++mt) {
        int r = wm * 32 + mt * 16 + (lid >> 2);
#pragma unroll
        for (int nt = 0; nt < 4; ++nt) {
            int c0 = wn * 32 + nt * 8 + (lid & 3) * 2;
            lg[r * 129 + c0]           = acc[mt][nt][0];
            lg[r * 129 + c0 + 1]       = acc[mt][nt][1];
            lg[(r + 8) * 129 + c0]     = acc[mt][nt][2];
            lg[(r + 8) * 129 + c0 + 1] = acc[mt][nt][3];
        }
    }
    __syncthreads();

    double ps_d = 0.0, sq_d = 0.0;
    if (t < TM) {
        const int r = t;
        float m = -INFINITY;
        for (int e = 0; e < E_EXP; ++e) {
            float cl = lg[r * 129 + e]      * 0.015625f;
            float nr = lg[r * 129 + 64 + e] * 0.015625f;
            float sd = (nr > 20.f) ? nr : log1pf(__expf(nr));
            float v  = cl + nsrs[r * 65 + e] * sd;
            lg[r * 129 + e] = v;
            m = fmaxf(m, v);
        }
        float s = 0.f;
        for (int e = 0; e < E_EXP; ++e) s += __expf(lg[r * 129 + e] - m);
        float inv = 1.f / s;
        float ps = 0.f, sq = 0.f;
        for (int e = 0; e < E_EXP; ++e) {
            float p = __expf(lg[r * 129 + e] - m) * inv;
            ps += p; sq += p * p;
        }
        ps_d = ps; sq_d = sq;

        unsigned long long sel = 0ULL;
        float m8 = 0.f;
        for (int kk = 0; kk < K_TOP; ++kk) {
            float best = -INFINITY; int bi = 0;
            for (int e = 0; e < E_EXP; ++e) {
                if (!((sel >> e) & 1ULL)) {
                    float v = lg[r * 129 + e];
                    if (v > best) { best = v; bi = e; }
                }
            }
            sel |= 1ULL << bi;
            if (kk == 0) m8 = best;
        }
        float s8 = 0.f;
        for (int e = 0; e < E_EXP; ++e)
            if ((sel >> e) & 1ULL) s8 += __expf(lg[r * 129 + e] - m8);
        float inv8 = 1.f / s8;
        for (int e = 0; e < E_EXP; ++e)
            nsrs[r * 65 + e] = ((sel >> e) & 1ULL) ? __expf(lg[r * 129 + e] - m8) * inv8 : 0.f;
    }

    __shared__ double wps[4], wsq[4];
#pragma unroll
    for (int o = 16; o > 0; o >>= 1) {
        ps_d += __shfl_down_sync(0xffffffffu, ps_d, o);
        sq_d += __shfl_down_sync(0xffffffffu, sq_d, o);
    }
    if (wid < 4 && lid == 0) { wps[wid] = ps_d; wsq[wid] = sq_d; }
    __syncthreads();
    if (t == 0) {
        g_ps[blockIdx.x] = wps[0] + wps[1] + wps[2] + wps[3];
        g_sq[blockIdx.x] = wsq[0] + wsq[1] + wsq[2] + wsq[3];
    }
#pragma unroll
    for (int i = 0; i < 16; i++) {
        int idx = t + (i << 9);
        size_t o = (size_t)row0 * E_EXP + idx;
        if (o < (size_t)out_elems) out[o] = nsrs[(idx >> 6) * 65 + (idx & 63)];
    }
}

__global__ void finalize_kernel(float* __restrict__ out, int out_elems)
{
    __shared__ double ssum[256], ssq[256];
    double a = 0.0, b = 0.0;
    for (int i = threadIdx.x; i < NBLK; i += 256) { a += g_ps[i]; b += g_sq[i]; }
    ssum[threadIdx.x] = a; ssq[threadIdx.x] = b;
    __syncthreads();
    for (int s = 128; s > 0; s >>= 1) {
        if (threadIdx.x < s) {
            ssum[threadIdx.x] += ssum[threadIdx.x + s];
            ssq[threadIdx.x]  += ssq[threadIdx.x + s];
        }
        __syncthreads();
    }
    if (threadIdx.x == 0) {
        double n    = (double)B_TOK * (double)E_EXP;
        double mean = ssum[0] / n;
        double var  = (ssq[0] - n * mean * mean) / (n - 1.0);
        float loss  = (float)(var / (mean * mean + 1e-10));
        long long base = (long long)B_TOK * E_EXP;
        if (out_elems == 1) out[0] = loss;
        else for (long long i = base; i < (long long)out_elems; i++) out[i] = loss;
    }
}

extern "C" void kernel_launch(void* const* d_in, const int* in_sizes, int n_in,
                              void* d_out, int out_size)
{
    const float* x  = (const float*)d_in[0];
    const float* wg = (const float*)d_in[1];
    const float* wn = (const float*)d_in[2];
    const float* nz = (const float*)d_in[3];
    float* out = (float*)d_out;

    cudaFuncSetAttribute(gate_mma_kernel, cudaFuncAttributeMaxDynamicSharedMemorySize, SMEM_BYTES);

    wconv_kernel<<<(D_DIM * E_EXP + 255) / 256, 256>>>(wg, wn);
    gate_mma_kernel<<<NBLK, 512, SMEM_BYTES>>>(x, nz, out, out_size);
    finalize_kernel<<<1, 256>>>(out, out_size);
}